// round 4
// baseline (speedup 1.0000x reference)
#include <cuda_runtime.h>
#include <cuda_bf16.h>
#include <math.h>

#define NN 50000
#define NE 800000
#define NG 64
#define FI 128
#define FH 192
#define FO 128
#define NC 10

// ---------------- device scratch ----------------
__device__ int   g_deg[NN];
__device__ int   g_fill[NN];
__device__ float g_dis[NN];
__device__ int   g_rowptr[NN + 1];
__device__ int   g_bsum[256];
__device__ int   g_boff[256];
__device__ int   g_colidx[NE];
__device__ float g_ew[NE];

__device__ float g_t1[(size_t)NN * FH];
__device__ float g_t2[(size_t)NN * FH];
__device__ float g_hA[(size_t)NN * FH];
__device__ float g_hB[(size_t)NN * FH];
__device__ __nv_bfloat16 g_xb[(size_t)NN * FI];    // bf16 gather source: x
__device__ __nv_bfloat16 g_hb[(size_t)NN * FH];    // bf16 gather source: layer outputs
__device__ __nv_bfloat16 g_t1b[(size_t)NN * FH];   // bf16 gather source: T1
__device__ float g_wcat[3 * FH * FH];
__device__ float g_pool[NG * FO];
__device__ int   g_cnt[NG];

__device__ __forceinline__ float2 bfu2f2(unsigned u) {
    __nv_bfloat162 b = *reinterpret_cast<__nv_bfloat162*>(&u);
    return __bfloat1622float2(b);
}

// ---------------- graph prep ----------------
__global__ void zero_kernel() {
    int i = blockIdx.x * blockDim.x + threadIdx.x;
    if (i < NN) { g_deg[i] = 0; g_fill[i] = 0; }
    if (i < NG * FO) g_pool[i] = 0.f;
    if (i < NG) g_cnt[i] = 0;
}

__global__ void hist_kernel(const int* __restrict__ ei) {
    int e = blockIdx.x * blockDim.x + threadIdx.x;
    if (e < NE) atomicAdd(&g_deg[ei[e]], 1);
}

__global__ void dis_kernel() {
    int i = blockIdx.x * blockDim.x + threadIdx.x;
    if (i < NN) {
        int d = g_deg[i];
        g_dis[i] = (d > 0) ? rsqrtf((float)d) : 0.f;
    }
}

__global__ void conv_x_kernel(const float* __restrict__ x) {
    int i = blockIdx.x * blockDim.x + threadIdx.x;
    if (i < NN * FI / 4) {
        float4 v = __ldg(reinterpret_cast<const float4*>(x) + i);
        __nv_bfloat162 a = __float22bfloat162_rn(make_float2(v.x, v.y));
        __nv_bfloat162 b = __float22bfloat162_rn(make_float2(v.z, v.w));
        reinterpret_cast<__nv_bfloat162*>(g_xb)[2 * i] = a;
        reinterpret_cast<__nv_bfloat162*>(g_xb)[2 * i + 1] = b;
    }
}

// hierarchical scan
__global__ void scan1_kernel() {
    __shared__ int ws[8];
    int t = threadIdx.x, b = blockIdx.x;
    int lane = t & 31, w = t >> 5;
    int i = b * 256 + t;
    int v = (i < NN) ? g_deg[i] : 0;
    int incl = v;
#pragma unroll
    for (int d = 1; d < 32; d <<= 1) {
        int n = __shfl_up_sync(0xffffffff, incl, d);
        if (lane >= d) incl += n;
    }
    if (lane == 31) ws[w] = incl;
    __syncthreads();
    if (w == 0 && lane < 8) {
        int s = ws[lane];
#pragma unroll
        for (int d = 1; d < 8; d <<= 1) {
            int n = __shfl_up_sync(0xff, s, d);
            if (lane >= d) s += n;
        }
        ws[lane] = s;
    }
    __syncthreads();
    int off = (w > 0) ? ws[w - 1] : 0;
    incl += off;
    if (i < NN) g_rowptr[i + 1] = incl;
    if (t == 255) g_bsum[b] = incl;
}

__global__ void scan2_kernel(int nblk) {
    __shared__ int ws[8];
    int t = threadIdx.x;
    int lane = t & 31, w = t >> 5;
    int v = (t < nblk) ? g_bsum[t] : 0;
    int incl = v;
#pragma unroll
    for (int d = 1; d < 32; d <<= 1) {
        int n = __shfl_up_sync(0xffffffff, incl, d);
        if (lane >= d) incl += n;
    }
    if (lane == 31) ws[w] = incl;
    __syncthreads();
    if (w == 0 && lane < 8) {
        int s = ws[lane];
#pragma unroll
        for (int d = 1; d < 8; d <<= 1) {
            int n = __shfl_up_sync(0xff, s, d);
            if (lane >= d) s += n;
        }
        ws[lane] = s;
    }
    __syncthreads();
    int off = (w > 0) ? ws[w - 1] : 0;
    g_boff[t] = incl + off - v;
    if (t == 0) g_rowptr[0] = 0;
}

__global__ void scan3_kernel() {
    int i = blockIdx.x * blockDim.x + threadIdx.x;
    if (i < NN) g_rowptr[i + 1] += g_boff[i >> 8];
}

__global__ void fill_kernel(const int* __restrict__ ei) {
    int e = blockIdx.x * blockDim.x + threadIdx.x;
    if (e >= NE) return;
    int r = ei[e];
    int c = ei[NE + e];
    int p = g_rowptr[r] + atomicAdd(&g_fill[r], 1);
    g_colidx[p] = c;
    g_ew[p] = -g_dis[r] * g_dis[c];
}

// ---------------- SpMM: bf16 gather, fp32 accumulate, batched MLP=8 ----------------
template <int F, bool WB16>
__global__ void spmm_kernel(const __nv_bfloat16* __restrict__ hin,
                            float* __restrict__ hout,
                            __nv_bfloat16* __restrict__ bout) {
    int gw = (int)((blockIdx.x * (size_t)blockDim.x + threadIdx.x) >> 5);
    int lane = threadIdx.x & 31;
    if (gw >= NN) return;
    int s = g_rowptr[gw];
    int e = g_rowptr[gw + 1];
    float acc[6];
#pragma unroll
    for (int v = 0; v < 6; v++) acc[v] = 0.f;

    for (int base = s; base < e; base += 32) {
        int idx = base + lane;
        int c = 0; float w = 0.f;
        if (idx < e) { c = __ldg(&g_colidx[idx]); w = __ldg(&g_ew[idx]); }
        int n = min(32, e - base);
        for (int j = 0; j < n; j += 8) {
            int m = min(8, n - j);
            uint2 pa[8]; unsigned qa[8]; float wa[8];
#pragma unroll
            for (int u = 0; u < 8; u++) {
                if (u < m) {
                    int cj = __shfl_sync(0xffffffff, c, j + u);
                    wa[u] = __shfl_sync(0xffffffff, w, j + u);
                    const __nv_bfloat16* hr = hin + (size_t)cj * F;
                    pa[u] = __ldg(reinterpret_cast<const uint2*>(hr) + lane);
                    if (F == 192)
                        qa[u] = __ldg(reinterpret_cast<const unsigned*>(hr + 128) + lane);
                }
            }
#pragma unroll
            for (int u = 0; u < 8; u++) {
                if (u < m) {
                    float2 f0 = bfu2f2(pa[u].x);
                    float2 f1 = bfu2f2(pa[u].y);
                    acc[0] = fmaf(wa[u], f0.x, acc[0]);
                    acc[1] = fmaf(wa[u], f0.y, acc[1]);
                    acc[2] = fmaf(wa[u], f1.x, acc[2]);
                    acc[3] = fmaf(wa[u], f1.y, acc[3]);
                    if (F == 192) {
                        float2 f2 = bfu2f2(qa[u]);
                        acc[4] = fmaf(wa[u], f2.x, acc[4]);
                        acc[5] = fmaf(wa[u], f2.y, acc[5]);
                    }
                }
            }
        }
    }

    // fp32 out: first 128 features as float4 per lane; tail (F=192) as float2
    float* o = hout + (size_t)gw * F;
    reinterpret_cast<float4*>(o)[lane] = make_float4(acc[0], acc[1], acc[2], acc[3]);
    if (F == 192)
        reinterpret_cast<float2*>(o + 128)[lane] = make_float2(acc[4], acc[5]);
    if (WB16) {
        __nv_bfloat16* b = bout + (size_t)gw * F;
        uint2 p;
        __nv_bfloat162 b0 = __float22bfloat162_rn(make_float2(acc[0], acc[1]));
        __nv_bfloat162 b1 = __float22bfloat162_rn(make_float2(acc[2], acc[3]));
        p.x = *reinterpret_cast<unsigned*>(&b0);
        p.y = *reinterpret_cast<unsigned*>(&b1);
        reinterpret_cast<uint2*>(b)[lane] = p;
        if (F == 192) {
            __nv_bfloat162 b2 = __float22bfloat162_rn(make_float2(acc[4], acc[5]));
            reinterpret_cast<unsigned*>(b + 128)[lane] = *reinterpret_cast<unsigned*>(&b2);
        }
    }
}

// ---------------- weight fold ----------------
__global__ void prep_wcat(const float* __restrict__ W, int finfo) {
    int i = blockIdx.x * blockDim.x + threadIdx.x;
    if (i >= finfo) return;
    float w0 = W[i], w1 = W[finfo + i], w2 = W[2 * finfo + i];
    g_wcat[i] = w0 - w2;
    g_wcat[finfo + i] = w1;
    g_wcat[2 * finfo + i] = 2.f * w2;
}

// ---------------- TF32 tensor-core GEMM ----------------
__device__ __forceinline__ unsigned f2tf(float f) {
    unsigned u;
    asm("cvt.rna.tf32.f32 %0, %1;" : "=r"(u) : "f"(f));
    return u;
}

#define MMA_TF32(c, A_, B_) \
    asm volatile("mma.sync.aligned.m16n8k8.row.col.f32.tf32.tf32.f32 " \
                 "{%0,%1,%2,%3},{%4,%5,%6,%7},{%8,%9},{%0,%1,%2,%3};" \
                 : "+f"((c)[0]), "+f"((c)[1]), "+f"((c)[2]), "+f"((c)[3]) \
                 : "r"((A_)[0]), "r"((A_)[1]), "r"((A_)[2]), "r"((A_)[3]), \
                   "r"((B_)[0]), "r"((B_)[1]))

__global__ __launch_bounds__(128) void gemm_cheb(
    const float* __restrict__ h, const float* __restrict__ t1p, const float* __restrict__ t2p,
    const float* __restrict__ bias, float* __restrict__ out,
    __nv_bfloat16* __restrict__ bout, int Fin, int Fo)
{
    __shared__ unsigned As[128 * 36];
    __shared__ unsigned BsH[32 * 72];
    __shared__ unsigned BsL[32 * 72];

    int tid = threadIdx.x;
    int lane = tid & 31;
    int warp = tid >> 5;
    int wm = warp >> 1;
    int wn = warp & 1;
    int tile_m = blockIdx.x * 128;
    int tile_n = blockIdx.y * 64;
    int K3 = 3 * Fin;
    const float* bufs[3] = { h, t1p, t2p };

    float acc[4][4][4];
#pragma unroll
    for (int a = 0; a < 4; a++)
#pragma unroll
        for (int b = 0; b < 4; b++)
#pragma unroll
            for (int c = 0; c < 4; c++) acc[a][b][c] = 0.f;

    for (int k0 = 0; k0 < K3; k0 += 32) {
        const float* A = bufs[k0 / Fin];
        int kl = k0 % Fin;
#pragma unroll
        for (int j = 0; j < 8; j++) {
            int idx = j * 128 + tid;
            int m = idx >> 3, kq = idx & 7;
            int gm = tile_m + m;
            float4 v = make_float4(0.f, 0.f, 0.f, 0.f);
            if (gm < NN) v = *reinterpret_cast<const float4*>(A + (size_t)gm * Fin + kl + kq * 4);
            uint4 u = make_uint4(f2tf(v.x), f2tf(v.y), f2tf(v.z), f2tf(v.w));
            *reinterpret_cast<uint4*>(&As[m * 36 + kq * 4]) = u;
        }
#pragma unroll
        for (int j = 0; j < 4; j++) {
            int idx = j * 128 + tid;
            int kr = idx >> 4, nq = idx & 15;
            float4 w = *reinterpret_cast<const float4*>(
                &g_wcat[(size_t)(k0 + kr) * Fo + tile_n + nq * 4]);
            unsigned hx = f2tf(w.x), hy = f2tf(w.y), hz = f2tf(w.z), hw = f2tf(w.w);
            uint4 lo = make_uint4(
                f2tf(w.x - __uint_as_float(hx)), f2tf(w.y - __uint_as_float(hy)),
                f2tf(w.z - __uint_as_float(hz)), f2tf(w.w - __uint_as_float(hw)));
            *reinterpret_cast<uint4*>(&BsH[kr * 72 + nq * 4]) = make_uint4(hx, hy, hz, hw);
            *reinterpret_cast<uint4*>(&BsL[kr * 72 + nq * 4]) = lo;
        }
        __syncthreads();

#pragma unroll
        for (int ks = 0; ks < 4; ks++) {
            int kk = ks * 8;
            unsigned a[4][4], bh[4][2], bl[4][2];
#pragma unroll
            for (int mt = 0; mt < 4; mt++) {
                int r = (wm * 64 + mt * 16 + (lane >> 2)) * 36 + kk + (lane & 3);
                a[mt][0] = As[r];
                a[mt][1] = As[r + 8 * 36];
                a[mt][2] = As[r + 4];
                a[mt][3] = As[r + 8 * 36 + 4];
            }
#pragma unroll
            for (int nt = 0; nt < 4; nt++) {
                int c = wn * 32 + nt * 8 + (lane >> 2);
                bh[nt][0] = BsH[(kk + (lane & 3)) * 72 + c];
                bh[nt][1] = BsH[(kk + 4 + (lane & 3)) * 72 + c];
                bl[nt][0] = BsL[(kk + (lane & 3)) * 72 + c];
                bl[nt][1] = BsL[(kk + 4 + (lane & 3)) * 72 + c];
            }
#pragma unroll
            for (int mt = 0; mt < 4; mt++)
#pragma unroll
                for (int nt = 0; nt < 4; nt++) {
                    MMA_TF32(acc[mt][nt], a[mt], bh[nt]);
                    MMA_TF32(acc[mt][nt], a[mt], bl[nt]);
                }
        }
        __syncthreads();
    }

#pragma unroll
    for (int mt = 0; mt < 4; mt++) {
        int r0 = tile_m + wm * 64 + mt * 16 + (lane >> 2);
#pragma unroll
        for (int nt = 0; nt < 4; nt++) {
            int c0 = tile_n + wn * 32 + nt * 8 + 2 * (lane & 3);
            float2 bb = *reinterpret_cast<const float2*>(bias + c0);
            if (r0 < NN) {
                float2 o = make_float2(acc[mt][nt][0] + bb.x, acc[mt][nt][1] + bb.y);
                *reinterpret_cast<float2*>(out + (size_t)r0 * Fo + c0) = o;
                if (bout) {
                    __nv_bfloat162 ob = __float22bfloat162_rn(o);
                    *reinterpret_cast<__nv_bfloat162*>(bout + (size_t)r0 * Fo + c0) = ob;
                }
            }
            if (r0 + 8 < NN) {
                float2 o = make_float2(acc[mt][nt][2] + bb.x, acc[mt][nt][3] + bb.y);
                *reinterpret_cast<float2*>(out + (size_t)(r0 + 8) * Fo + c0) = o;
                if (bout) {
                    __nv_bfloat162 ob = __float22bfloat162_rn(o);
                    *reinterpret_cast<__nv_bfloat162*>(bout + (size_t)(r0 + 8) * Fo + c0) = ob;
                }
            }
        }
    }
}

// ---------------- global mean pool ----------------
__global__ void pool_kernel(const float* __restrict__ h, const int* __restrict__ batch) {
    int t = threadIdx.x;
    int base = blockIdx.x * 128;
    int cur = -1;
    float acc = 0.f;
    int cnt = 0;
    for (int n = 0; n < 128; n++) {
        int g = base + n;
        if (g >= NN) break;
        int bg = batch[g];
        if (bg != cur) {
            if (cur >= 0) {
                atomicAdd(&g_pool[cur * FO + t], acc);
                if (t == 0) atomicAdd(&g_cnt[cur], cnt);
            }
            cur = bg; acc = 0.f; cnt = 0;
        }
        acc += h[(size_t)g * FO + t];
        cnt++;
    }
    if (cur >= 0) {
        atomicAdd(&g_pool[cur * FO + t], acc);
        if (t == 0) atomicAdd(&g_cnt[cur], cnt);
    }
}

// ---------------- FC + log_softmax ----------------
__global__ void final_kernel(const float* __restrict__ fcw, const float* __restrict__ fcb,
                             float* __restrict__ out) {
    __shared__ float lg[NG][NC];
    __shared__ float smax[NG], slse[NG];
    int t = threadIdx.x;
    if (t < NG * NC) {
        int g = t / NC, c = t % NC;
        float inv = 1.f / fmaxf((float)g_cnt[g], 1.f);
        float s = fcb[c];
        for (int f = 0; f < FO; f++)
            s = fmaf(g_pool[g * FO + f] * inv, fcw[f * NC + c], s);
        lg[g][c] = s;
    }
    __syncthreads();
    if (t < NG) {
        float m = -1e30f;
        for (int c = 0; c < NC; c++) m = fmaxf(m, lg[t][c]);
        float se = 0.f;
        for (int c = 0; c < NC; c++) se += expf(lg[t][c] - m);
        smax[t] = m;
        slse[t] = logf(se);
    }
    __syncthreads();
    if (t < NG * NC) {
        int g = t / NC, c = t % NC;
        out[t] = lg[g][c] - smax[g] - slse[g];
    }
}

// ---------------- launch ----------------
extern "C" void kernel_launch(void* const* d_in, const int* in_sizes, int n_in,
                              void* d_out, int out_size) {
    const float* x   = (const float*)d_in[0];
    const int*   ei  = (const int*)d_in[1];
    const int*   bat = (const int*)d_in[2];
    const float* W1  = (const float*)d_in[3];
    const float* b1  = (const float*)d_in[4];
    const float* W2  = (const float*)d_in[5];
    const float* b2  = (const float*)d_in[6];
    const float* W3  = (const float*)d_in[7];
    const float* b3  = (const float*)d_in[8];
    const float* fcw = (const float*)d_in[9];
    const float* fcb = (const float*)d_in[10];
    float* out = (float*)d_out;

    float *t1, *t2, *hA, *hB;
    __nv_bfloat16 *xb, *hb, *t1b;
    cudaGetSymbolAddress((void**)&t1, g_t1);
    cudaGetSymbolAddress((void**)&t2, g_t2);
    cudaGetSymbolAddress((void**)&hA, g_hA);
    cudaGetSymbolAddress((void**)&hB, g_hB);
    cudaGetSymbolAddress((void**)&xb, g_xb);
    cudaGetSymbolAddress((void**)&hb, g_hb);
    cudaGetSymbolAddress((void**)&t1b, g_t1b);

    const int NB = (NN + 255) / 256;

    zero_kernel<<<(NN + 255) / 256, 256>>>();
    hist_kernel<<<(NE + 255) / 256, 256>>>(ei);
    dis_kernel<<<(NN + 255) / 256, 256>>>();
    conv_x_kernel<<<(NN * FI / 4 + 255) / 256, 256>>>(x);
    scan1_kernel<<<NB, 256>>>();
    scan2_kernel<<<1, 256>>>(NB);
    scan3_kernel<<<NB, 256>>>();
    fill_kernel<<<(NE + 255) / 256, 256>>>(ei);

    const int spmmBlocks = (NN * 32 + 255) / 256;
    dim3 gemmGridH((NN + 127) / 128, FH / 64);
    dim3 gemmGridO((NN + 127) / 128, FO / 64);

    // layer 1: Fin=128 -> Fo=192
    spmm_kernel<FI, true ><<<spmmBlocks, 256>>>(xb, t1, t1b);
    spmm_kernel<FI, false><<<spmmBlocks, 256>>>(t1b, t2, nullptr);
    prep_wcat<<<(FI * FH + 255) / 256, 256>>>(W1, FI * FH);
    gemm_cheb<<<gemmGridH, 128>>>(x, t1, t2, b1, hA, hb, FI, FH);

    // layer 2: Fin=192 -> Fo=192
    spmm_kernel<FH, true ><<<spmmBlocks, 256>>>(hb, t1, t1b);
    spmm_kernel<FH, false><<<spmmBlocks, 256>>>(t1b, t2, nullptr);
    prep_wcat<<<(FH * FH + 255) / 256, 256>>>(W2, FH * FH);
    gemm_cheb<<<gemmGridH, 128>>>(hA, t1, t2, b2, hB, hb, FH, FH);

    // layer 3: Fin=192 -> Fo=128
    spmm_kernel<FH, true ><<<spmmBlocks, 256>>>(hb, t1, t1b);
    spmm_kernel<FH, false><<<spmmBlocks, 256>>>(t1b, t2, nullptr);
    prep_wcat<<<(FH * FO + 255) / 256, 256>>>(W3, FH * FO);
    gemm_cheb<<<gemmGridO, 128>>>(hB, t1, t2, b3, hA, nullptr, FH, FO);

    pool_kernel<<<(NN + 127) / 128, 128>>>(hA, bat);
    final_kernel<<<1, 640>>>(fcw, fcb, out);
}

// round 11
// speedup vs baseline: 1.9582x; 1.9582x over previous
#include <cuda_runtime.h>
#include <cuda_bf16.h>
#include <stdint.h>
#include <math.h>

#define NN 50000
#define NE 800000
#define NG 64
#define FI 128
#define FH 192
#define FO 128
#define NC 10

// ---------------- device scratch ----------------
__device__ int   g_deg[NN];
__device__ int   g_fill[NN];
__device__ float g_dis[NN];
__device__ int   g_rowptr[NN + 1];
__device__ int   g_bsum[256];
__device__ int   g_boff[256];
__device__ int   g_colidx[NE];
__device__ float g_ew[NE];

__device__ __align__(16) __nv_bfloat16 g_xb[(size_t)NN * FI];
__device__ __align__(16) __nv_bfloat16 g_t1b[(size_t)NN * FH];
__device__ __align__(16) __nv_bfloat16 g_t2b[(size_t)NN * FH];
__device__ __align__(16) __nv_bfloat16 g_h1b[(size_t)NN * FH];
__device__ __align__(16) __nv_bfloat16 g_h2b[(size_t)NN * FH];
__device__ __align__(16) __nv_bfloat16 g_h3b[(size_t)NN * FO];
__device__ float g_wcat[3 * FH * FH];      // [K3][Fo] folded fp32 weights
__device__ float g_pool[NG * FO];
__device__ int   g_cnt[NG];

__device__ __forceinline__ float2 bfu2f2(unsigned u) {
    __nv_bfloat162 b = *reinterpret_cast<__nv_bfloat162*>(&u);
    return __bfloat1622float2(b);
}

// ---------------- graph prep ----------------
__global__ void zero_kernel() {
    int i = blockIdx.x * blockDim.x + threadIdx.x;
    if (i < NN) { g_deg[i] = 0; g_fill[i] = 0; }
    if (i < NG * FO) g_pool[i] = 0.f;
    if (i < NG) g_cnt[i] = 0;
}
__global__ void hist_kernel(const int* __restrict__ ei) {
    int e = blockIdx.x * blockDim.x + threadIdx.x;
    if (e < NE) atomicAdd(&g_deg[ei[e]], 1);
}
__global__ void dis_kernel() {
    int i = blockIdx.x * blockDim.x + threadIdx.x;
    if (i < NN) {
        int d = g_deg[i];
        g_dis[i] = (d > 0) ? rsqrtf((float)d) : 0.f;
    }
}
__global__ void conv_x_kernel(const float* __restrict__ x) {
    int i = blockIdx.x * blockDim.x + threadIdx.x;
    if (i < NN * FI / 4) {
        float4 v = __ldg(reinterpret_cast<const float4*>(x) + i);
        __nv_bfloat162 a = __float22bfloat162_rn(make_float2(v.x, v.y));
        __nv_bfloat162 b = __float22bfloat162_rn(make_float2(v.z, v.w));
        reinterpret_cast<__nv_bfloat162*>(g_xb)[2 * i] = a;
        reinterpret_cast<__nv_bfloat162*>(g_xb)[2 * i + 1] = b;
    }
}
__global__ void scan1_kernel() {
    __shared__ int ws[8];
    int t = threadIdx.x, b = blockIdx.x;
    int lane = t & 31, w = t >> 5;
    int i = b * 256 + t;
    int v = (i < NN) ? g_deg[i] : 0;
    int incl = v;
#pragma unroll
    for (int d = 1; d < 32; d <<= 1) {
        int n = __shfl_up_sync(0xffffffff, incl, d);
        if (lane >= d) incl += n;
    }
    if (lane == 31) ws[w] = incl;
    __syncthreads();
    if (w == 0 && lane < 8) {
        int s = ws[lane];
#pragma unroll
        for (int d = 1; d < 8; d <<= 1) {
            int n = __shfl_up_sync(0xff, s, d);
            if (lane >= d) s += n;
        }
        ws[lane] = s;
    }
    __syncthreads();
    int off = (w > 0) ? ws[w - 1] : 0;
    incl += off;
    if (i < NN) g_rowptr[i + 1] = incl;
    if (t == 255) g_bsum[b] = incl;
}
__global__ void scan2_kernel(int nblk) {
    __shared__ int ws[8];
    int t = threadIdx.x;
    int lane = t & 31, w = t >> 5;
    int v = (t < nblk) ? g_bsum[t] : 0;
    int incl = v;
#pragma unroll
    for (int d = 1; d < 32; d <<= 1) {
        int n = __shfl_up_sync(0xffffffff, incl, d);
        if (lane >= d) incl += n;
    }
    if (lane == 31) ws[w] = incl;
    __syncthreads();
    if (w == 0 && lane < 8) {
        int s = ws[lane];
#pragma unroll
        for (int d = 1; d < 8; d <<= 1) {
            int n = __shfl_up_sync(0xff, s, d);
            if (lane >= d) s += n;
        }
        ws[lane] = s;
    }
    __syncthreads();
    int off = (w > 0) ? ws[w - 1] : 0;
    g_boff[t] = incl + off - v;
    if (t == 0) g_rowptr[0] = 0;
}
__global__ void scan3_kernel() {
    int i = blockIdx.x * blockDim.x + threadIdx.x;
    if (i < NN) g_rowptr[i + 1] += g_boff[i >> 8];
}
__global__ void fill_kernel(const int* __restrict__ ei) {
    int e = blockIdx.x * blockDim.x + threadIdx.x;
    if (e >= NE) return;
    int r = ei[e];
    int c = ei[NE + e];
    int p = g_rowptr[r] + atomicAdd(&g_fill[r], 1);
    g_colidx[p] = c;
    g_ew[p] = -g_dis[r] * g_dis[c];
}

// ---------------- SpMM: bf16 gather, fp32 accumulate, bf16 out ----------------
template <int F>
__global__ void spmm_kernel(const __nv_bfloat16* __restrict__ hin,
                            __nv_bfloat16* __restrict__ bout) {
    int gw = (int)((blockIdx.x * (size_t)blockDim.x + threadIdx.x) >> 5);
    int lane = threadIdx.x & 31;
    if (gw >= NN) return;
    int s = g_rowptr[gw];
    int e = g_rowptr[gw + 1];
    float a0 = 0.f, a1 = 0.f, a2 = 0.f, a3 = 0.f, a4 = 0.f, a5 = 0.f;
    int i = s;
    for (; i + 4 <= e; i += 4) {
        int c0 = __ldg(&g_colidx[i]),     c1 = __ldg(&g_colidx[i + 1]);
        int c2 = __ldg(&g_colidx[i + 2]), c3 = __ldg(&g_colidx[i + 3]);
        float w0 = __ldg(&g_ew[i]),     w1 = __ldg(&g_ew[i + 1]);
        float w2 = __ldg(&g_ew[i + 2]), w3 = __ldg(&g_ew[i + 3]);
        uint2 p0 = __ldg(reinterpret_cast<const uint2*>(hin + (size_t)c0 * F) + lane);
        uint2 p1 = __ldg(reinterpret_cast<const uint2*>(hin + (size_t)c1 * F) + lane);
        uint2 p2 = __ldg(reinterpret_cast<const uint2*>(hin + (size_t)c2 * F) + lane);
        uint2 p3 = __ldg(reinterpret_cast<const uint2*>(hin + (size_t)c3 * F) + lane);
        unsigned q0 = 0, q1 = 0, q2 = 0, q3 = 0;
        if (F == 192) {
            q0 = __ldg(reinterpret_cast<const unsigned*>(hin + (size_t)c0 * F + 128) + lane);
            q1 = __ldg(reinterpret_cast<const unsigned*>(hin + (size_t)c1 * F + 128) + lane);
            q2 = __ldg(reinterpret_cast<const unsigned*>(hin + (size_t)c2 * F + 128) + lane);
            q3 = __ldg(reinterpret_cast<const unsigned*>(hin + (size_t)c3 * F + 128) + lane);
        }
#define CONS(P, Q, W) { \
        float2 f0 = bfu2f2(P.x), f1 = bfu2f2(P.y); \
        a0 = fmaf(W, f0.x, a0); a1 = fmaf(W, f0.y, a1); \
        a2 = fmaf(W, f1.x, a2); a3 = fmaf(W, f1.y, a3); \
        if (F == 192) { float2 f2 = bfu2f2(Q); a4 = fmaf(W, f2.x, a4); a5 = fmaf(W, f2.y, a5); } }
        CONS(p0, q0, w0); CONS(p1, q1, w1); CONS(p2, q2, w2); CONS(p3, q3, w3);
    }
    for (; i < e; i++) {
        int c = __ldg(&g_colidx[i]);
        float w = __ldg(&g_ew[i]);
        uint2 p = __ldg(reinterpret_cast<const uint2*>(hin + (size_t)c * F) + lane);
        unsigned q = 0;
        if (F == 192) q = __ldg(reinterpret_cast<const unsigned*>(hin + (size_t)c * F + 128) + lane);
        CONS(p, q, w);
    }
#undef CONS
    __nv_bfloat16* b = bout + (size_t)gw * F;
    __nv_bfloat162 b0 = __float22bfloat162_rn(make_float2(a0, a1));
    __nv_bfloat162 b1 = __float22bfloat162_rn(make_float2(a2, a3));
    uint2 pp;
    pp.x = *reinterpret_cast<unsigned*>(&b0);
    pp.y = *reinterpret_cast<unsigned*>(&b1);
    reinterpret_cast<uint2*>(b)[lane] = pp;
    if (F == 192) {
        __nv_bfloat162 b2 = __float22bfloat162_rn(make_float2(a4, a5));
        reinterpret_cast<unsigned*>(b + 128)[lane] = *reinterpret_cast<unsigned*>(&b2);
    }
}

// ---------------- weight fold: wcat[k][o] = [W0 - W2 ; W1 ; 2*W2] (fp32) ----------------
__global__ void prep_wcat(const float* __restrict__ W, int finfo) {
    int i = blockIdx.x * blockDim.x + threadIdx.x;
    if (i >= finfo) return;
    float w0 = W[i], w1 = W[finfo + i], w2 = W[2 * finfo + i];
    g_wcat[i] = w0 - w2;
    g_wcat[finfo + i] = w1;
    g_wcat[2 * finfo + i] = 2.f * w2;
}

// ---------------- TF32 tensor-core GEMM (R3-verified structure, bf16 A in, bf16 out) ----------------
__device__ __forceinline__ unsigned f2tf(float f) {
    unsigned u;
    asm("cvt.rna.tf32.f32 %0, %1;" : "=r"(u) : "f"(f));
    return u;
}

#define MMA_TF32(c, A_, B_) \
    asm volatile("mma.sync.aligned.m16n8k8.row.col.f32.tf32.tf32.f32 " \
                 "{%0,%1,%2,%3},{%4,%5,%6,%7},{%8,%9},{%0,%1,%2,%3};" \
                 : "+f"((c)[0]), "+f"((c)[1]), "+f"((c)[2]), "+f"((c)[3]) \
                 : "r"((A_)[0]), "r"((A_)[1]), "r"((A_)[2]), "r"((A_)[3]), \
                   "r"((B_)[0]), "r"((B_)[1]))

__global__ __launch_bounds__(128) void gemm_cheb(
    const __nv_bfloat16* __restrict__ h, const __nv_bfloat16* __restrict__ t1p,
    const __nv_bfloat16* __restrict__ t2p, const float* __restrict__ bias,
    __nv_bfloat16* __restrict__ outb, int Fin, int Fo)
{
    __shared__ unsigned As[128 * 36];     // m-major, stride 36
    __shared__ unsigned BsH[32 * 72];     // k-major, stride 72
    __shared__ unsigned BsL[32 * 72];

    int tid = threadIdx.x;
    int lane = tid & 31;
    int warp = tid >> 5;
    int wm = warp >> 1;
    int wn = warp & 1;
    int tile_m = blockIdx.x * 128;
    int tile_n = blockIdx.y * 64;
    int K3 = 3 * Fin;
    const __nv_bfloat16* bufs[3] = { h, t1p, t2p };

    float acc[4][4][4];
#pragma unroll
    for (int a = 0; a < 4; a++)
#pragma unroll
        for (int b = 0; b < 4; b++)
#pragma unroll
            for (int c = 0; c < 4; c++) acc[a][b][c] = 0.f;

    for (int k0 = 0; k0 < K3; k0 += 32) {
        const __nv_bfloat16* A = bufs[k0 / Fin];
        int kl = k0 % Fin;
        // stage A: 128 rows x 32 k (bf16 -> tf32 via bit shift; bf16 ⊂ tf32 exactly)
#pragma unroll
        for (int j = 0; j < 4; j++) {
            int idx = j * 128 + tid;       // 512 ops
            int m = idx >> 2, kq = idx & 3; // kq = group of 8 k
            int gm = tile_m + m;
            uint4 v = make_uint4(0u, 0u, 0u, 0u);
            if (gm < NN)
                v = *reinterpret_cast<const uint4*>(A + (size_t)gm * Fin + kl + kq * 8);
            unsigned* dst = &As[m * 36 + kq * 8];
            dst[0] = (v.x & 0xFFFFu) << 16; dst[1] = v.x & 0xFFFF0000u;
            dst[2] = (v.y & 0xFFFFu) << 16; dst[3] = v.y & 0xFFFF0000u;
            dst[4] = (v.z & 0xFFFFu) << 16; dst[5] = v.z & 0xFFFF0000u;
            dst[6] = (v.w & 0xFFFFu) << 16; dst[7] = v.w & 0xFFFF0000u;
        }
        // stage B hi/lo: 32 k x 64 n from fp32 wcat
#pragma unroll
        for (int j = 0; j < 4; j++) {
            int idx = j * 128 + tid;
            int kr = idx >> 4, nq = idx & 15;
            float4 w = *reinterpret_cast<const float4*>(
                &g_wcat[(size_t)(k0 + kr) * Fo + tile_n + nq * 4]);
            unsigned hx = f2tf(w.x), hy = f2tf(w.y), hz = f2tf(w.z), hw = f2tf(w.w);
            uint4 lo = make_uint4(
                f2tf(w.x - __uint_as_float(hx)), f2tf(w.y - __uint_as_float(hy)),
                f2tf(w.z - __uint_as_float(hz)), f2tf(w.w - __uint_as_float(hw)));
            *reinterpret_cast<uint4*>(&BsH[kr * 72 + nq * 4]) = make_uint4(hx, hy, hz, hw);
            *reinterpret_cast<uint4*>(&BsL[kr * 72 + nq * 4]) = lo;
        }
        __syncthreads();

#pragma unroll
        for (int ks = 0; ks < 4; ks++) {
            int kk = ks * 8;
            unsigned a[4][4], bh[4][2], bl[4][2];
#pragma unroll
            for (int mt = 0; mt < 4; mt++) {
                int r = (wm * 64 + mt * 16 + (lane >> 2)) * 36 + kk + (lane & 3);
                a[mt][0] = As[r];
                a[mt][1] = As[r + 8 * 36];
                a[mt][2] = As[r + 4];
                a[mt][3] = As[r + 8 * 36 + 4];
            }
#pragma unroll
            for (int nt = 0; nt < 4; nt++) {
                int c = wn * 32 + nt * 8 + (lane >> 2);
                bh[nt][0] = BsH[(kk + (lane & 3)) * 72 + c];
                bh[nt][1] = BsH[(kk + 4 + (lane & 3)) * 72 + c];
                bl[nt][0] = BsL[(kk + (lane & 3)) * 72 + c];
                bl[nt][1] = BsL[(kk + 4 + (lane & 3)) * 72 + c];
            }
#pragma unroll
            for (int mt = 0; mt < 4; mt++)
#pragma unroll
                for (int nt = 0; nt < 4; nt++) {
                    MMA_TF32(acc[mt][nt], a[mt], bh[nt]);
                    MMA_TF32(acc[mt][nt], a[mt], bl[nt]);
                }
        }
        __syncthreads();
    }

    // epilogue: bf16 output
#pragma unroll
    for (int mt = 0; mt < 4; mt++) {
        int r0 = tile_m + wm * 64 + mt * 16 + (lane >> 2);
#pragma unroll
        for (int nt = 0; nt < 4; nt++) {
            int c0 = tile_n + wn * 32 + nt * 8 + 2 * (lane & 3);
            float2 bb = *reinterpret_cast<const float2*>(bias + c0);
            if (r0 < NN) {
                __nv_bfloat162 o = __float22bfloat162_rn(
                    make_float2(acc[mt][nt][0] + bb.x, acc[mt][nt][1] + bb.y));
                *reinterpret_cast<__nv_bfloat162*>(outb + (size_t)r0 * Fo + c0) = o;
            }
            if (r0 + 8 < NN) {
                __nv_bfloat162 o = __float22bfloat162_rn(
                    make_float2(acc[mt][nt][2] + bb.x, acc[mt][nt][3] + bb.y));
                *reinterpret_cast<__nv_bfloat162*>(outb + (size_t)(r0 + 8) * Fo + c0) = o;
            }
        }
    }
}

// ---------------- global mean pool (bf16 input) ----------------
__global__ void pool_kernel(const __nv_bfloat16* __restrict__ h, const int* __restrict__ batch) {
    int t = threadIdx.x;
    int base = blockIdx.x * 128;
    int cur = -1;
    float acc = 0.f;
    int cnt = 0;
    for (int n = 0; n < 128; n++) {
        int g = base + n;
        if (g >= NN) break;
        int bg = batch[g];
        if (bg != cur) {
            if (cur >= 0) {
                atomicAdd(&g_pool[cur * FO + t], acc);
                if (t == 0) atomicAdd(&g_cnt[cur], cnt);
            }
            cur = bg; acc = 0.f; cnt = 0;
        }
        acc += __bfloat162float(h[(size_t)g * FO + t]);
        cnt++;
    }
    if (cur >= 0) {
        atomicAdd(&g_pool[cur * FO + t], acc);
        if (t == 0) atomicAdd(&g_cnt[cur], cnt);
    }
}

// ---------------- FC + log_softmax ----------------
__global__ void final_kernel(const float* __restrict__ fcw, const float* __restrict__ fcb,
                             float* __restrict__ out) {
    __shared__ float lg[NG][NC];
    __shared__ float smax[NG], slse[NG];
    int t = threadIdx.x;
    if (t < NG * NC) {
        int g = t / NC, c = t % NC;
        float inv = 1.f / fmaxf((float)g_cnt[g], 1.f);
        float s = fcb[c];
        for (int f = 0; f < FO; f++)
            s = fmaf(g_pool[g * FO + f] * inv, fcw[f * NC + c], s);
        lg[g][c] = s;
    }
    __syncthreads();
    if (t < NG) {
        float m = -1e30f;
        for (int c = 0; c < NC; c++) m = fmaxf(m, lg[t][c]);
        float se = 0.f;
        for (int c = 0; c < NC; c++) se += expf(lg[t][c] - m);
        smax[t] = m;
        slse[t] = logf(se);
    }
    __syncthreads();
    if (t < NG * NC) {
        int g = t / NC, c = t % NC;
        out[t] = lg[g][c] - smax[g] - slse[g];
    }
}

// ---------------- launch ----------------
extern "C" void kernel_launch(void* const* d_in, const int* in_sizes, int n_in,
                              void* d_out, int out_size) {
    const float* x   = (const float*)d_in[0];
    const int*   ei  = (const int*)d_in[1];
    const int*   bat = (const int*)d_in[2];
    const float* W1  = (const float*)d_in[3];
    const float* b1  = (const float*)d_in[4];
    const float* W2  = (const float*)d_in[5];
    const float* b2  = (const float*)d_in[6];
    const float* W3  = (const float*)d_in[7];
    const float* b3  = (const float*)d_in[8];
    const float* fcw = (const float*)d_in[9];
    const float* fcb = (const float*)d_in[10];
    float* out = (float*)d_out;

    __nv_bfloat16 *xb, *t1b, *t2b, *h1b, *h2b, *h3b;
    cudaGetSymbolAddress((void**)&xb,  g_xb);
    cudaGetSymbolAddress((void**)&t1b, g_t1b);
    cudaGetSymbolAddress((void**)&t2b, g_t2b);
    cudaGetSymbolAddress((void**)&h1b, g_h1b);
    cudaGetSymbolAddress((void**)&h2b, g_h2b);
    cudaGetSymbolAddress((void**)&h3b, g_h3b);

    const int NB = (NN + 255) / 256;

    zero_kernel<<<(NN + 255) / 256, 256>>>();
    hist_kernel<<<(NE + 255) / 256, 256>>>(ei);
    dis_kernel<<<(NN + 255) / 256, 256>>>();
    conv_x_kernel<<<(NN * FI / 4 + 255) / 256, 256>>>(x);
    scan1_kernel<<<NB, 256>>>();
    scan2_kernel<<<1, 256>>>(NB);
    scan3_kernel<<<NB, 256>>>();
    fill_kernel<<<(NE + 255) / 256, 256>>>(ei);

    const int spmmBlocks = (NN * 32 + 255) / 256;
    dim3 gemmGridH((NN + 127) / 128, FH / 64);
    dim3 gemmGridO((NN + 127) / 128, FO / 64);

    // layer 1: Fin=128 -> Fo=192
    spmm_kernel<FI><<<spmmBlocks, 256>>>(xb, t1b);
    spmm_kernel<FI><<<spmmBlocks, 256>>>(t1b, t2b);
    prep_wcat<<<(FI * FH + 255) / 256, 256>>>(W1, FI * FH);
    gemm_cheb<<<gemmGridH, 128>>>(xb, t1b, t2b, b1, h1b, FI, FH);

    // layer 2: Fin=192 -> Fo=192
    spmm_kernel<FH><<<spmmBlocks, 256>>>(h1b, t1b);
    spmm_kernel<FH><<<spmmBlocks, 256>>>(t1b, t2b);
    prep_wcat<<<(FH * FH + 255) / 256, 256>>>(W2, FH * FH);
    gemm_cheb<<<gemmGridH, 128>>>(h1b, t1b, t2b, b2, h2b, FH, FH);

    // layer 3: Fin=192 -> Fo=128
    spmm_kernel<FH><<<spmmBlocks, 256>>>(h2b, t1b);
    spmm_kernel<FH><<<spmmBlocks, 256>>>(t1b, t2b);
    prep_wcat<<<(FH * FO + 255) / 256, 256>>>(W3, FH * FO);
    gemm_cheb<<<gemmGridO, 128>>>(h2b, t1b, t2b, b3, h3b, FH, FO);

    pool_kernel<<<(NN + 127) / 128, 128>>>(h3b, bat);
    final_kernel<<<1, 640>>>(fcw, fcb, out);
}

// round 14
// speedup vs baseline: 2.4188x; 1.2352x over previous
#include <cuda_runtime.h>
#include <cuda_bf16.h>
#include <stdint.h>
#include <math.h>

#define NN 50000
#define NE 800000
#define NG 64
#define FI 128
#define FH 192
#define FO 128
#define NC 10

// ---------------- device scratch ----------------
__device__ int   g_deg[NN];
__device__ int   g_fill[NN];
__device__ float g_dis[NN];
__device__ int   g_rowptr[NN + 1];
__device__ int   g_bsum[256];
__device__ int   g_boff[256];
__device__ int   g_colidx[NE];
__device__ float g_ew[NE];

__device__ __align__(16) __nv_bfloat16 g_xb[(size_t)NN * FI];
__device__ __align__(16) __nv_bfloat16 g_t1b[(size_t)NN * FH];
__device__ __align__(16) __nv_bfloat16 g_t2b[(size_t)NN * FH];
__device__ __align__(16) __nv_bfloat16 g_h1b[(size_t)NN * FH];
__device__ __align__(16) __nv_bfloat16 g_h2b[(size_t)NN * FH];
__device__ __align__(16) __nv_bfloat16 g_h3b[(size_t)NN * FO];
__device__ __align__(16) __nv_bfloat16 g_wbh[FH * 3 * FH];   // [Fo][K3] hi (folded, transposed)
__device__ __align__(16) __nv_bfloat16 g_wbl[FH * 3 * FH];   // [Fo][K3] lo
__device__ float g_pool[NG * FO];
__device__ int   g_cnt[NG];

__device__ __forceinline__ float2 bfu2f2(unsigned u) {
    __nv_bfloat162 b = *reinterpret_cast<__nv_bfloat162*>(&u);
    return __bfloat1622float2(b);
}

// ---------------- graph prep ----------------
__global__ void zero_kernel() {
    int i = blockIdx.x * blockDim.x + threadIdx.x;
    if (i < NN) { g_deg[i] = 0; g_fill[i] = 0; }
    if (i < NG * FO) g_pool[i] = 0.f;
    if (i < NG) g_cnt[i] = 0;
}
__global__ void hist_kernel(const int* __restrict__ ei) {
    int e = blockIdx.x * blockDim.x + threadIdx.x;
    if (e < NE) atomicAdd(&g_deg[ei[e]], 1);
}
__global__ void dis_kernel() {
    int i = blockIdx.x * blockDim.x + threadIdx.x;
    if (i < NN) {
        int d = g_deg[i];
        g_dis[i] = (d > 0) ? rsqrtf((float)d) : 0.f;
    }
}
__global__ void conv_x_kernel(const float* __restrict__ x) {
    int i = blockIdx.x * blockDim.x + threadIdx.x;
    if (i < NN * FI / 4) {
        float4 v = __ldg(reinterpret_cast<const float4*>(x) + i);
        __nv_bfloat162 a = __float22bfloat162_rn(make_float2(v.x, v.y));
        __nv_bfloat162 b = __float22bfloat162_rn(make_float2(v.z, v.w));
        reinterpret_cast<__nv_bfloat162*>(g_xb)[2 * i] = a;
        reinterpret_cast<__nv_bfloat162*>(g_xb)[2 * i + 1] = b;
    }
}
__global__ void scan1_kernel() {
    __shared__ int ws[8];
    int t = threadIdx.x, b = blockIdx.x;
    int lane = t & 31, w = t >> 5;
    int i = b * 256 + t;
    int v = (i < NN) ? g_deg[i] : 0;
    int incl = v;
#pragma unroll
    for (int d = 1; d < 32; d <<= 1) {
        int n = __shfl_up_sync(0xffffffff, incl, d);
        if (lane >= d) incl += n;
    }
    if (lane == 31) ws[w] = incl;
    __syncthreads();
    if (w == 0 && lane < 8) {
        int s = ws[lane];
#pragma unroll
        for (int d = 1; d < 8; d <<= 1) {
            int n = __shfl_up_sync(0xff, s, d);
            if (lane >= d) s += n;
        }
        ws[lane] = s;
    }
    __syncthreads();
    int off = (w > 0) ? ws[w - 1] : 0;
    incl += off;
    if (i < NN) g_rowptr[i + 1] = incl;
    if (t == 255) g_bsum[b] = incl;
}
__global__ void scan2_kernel(int nblk) {
    __shared__ int ws[8];
    int t = threadIdx.x;
    int lane = t & 31, w = t >> 5;
    int v = (t < nblk) ? g_bsum[t] : 0;
    int incl = v;
#pragma unroll
    for (int d = 1; d < 32; d <<= 1) {
        int n = __shfl_up_sync(0xffffffff, incl, d);
        if (lane >= d) incl += n;
    }
    if (lane == 31) ws[w] = incl;
    __syncthreads();
    if (w == 0 && lane < 8) {
        int s = ws[lane];
#pragma unroll
        for (int d = 1; d < 8; d <<= 1) {
            int n = __shfl_up_sync(0xff, s, d);
            if (lane >= d) s += n;
        }
        ws[lane] = s;
    }
    __syncthreads();
    int off = (w > 0) ? ws[w - 1] : 0;
    g_boff[t] = incl + off - v;
    if (t == 0) g_rowptr[0] = 0;
}
__global__ void scan3_kernel() {
    int i = blockIdx.x * blockDim.x + threadIdx.x;
    if (i < NN) g_rowptr[i + 1] += g_boff[i >> 8];
}
__global__ void fill_kernel(const int* __restrict__ ei) {
    int e = blockIdx.x * blockDim.x + threadIdx.x;
    if (e >= NE) return;
    int r = ei[e];
    int c = ei[NE + e];
    int p = g_rowptr[r] + atomicAdd(&g_fill[r], 1);
    g_colidx[p] = c;
    g_ew[p] = -g_dis[r] * g_dis[c];
}

// ---------------- SpMM: bf16 gather, fp32 accumulate, bf16 out ----------------
template <int F>
__global__ void spmm_kernel(const __nv_bfloat16* __restrict__ hin,
                            __nv_bfloat16* __restrict__ bout) {
    int gw = (int)((blockIdx.x * (size_t)blockDim.x + threadIdx.x) >> 5);
    int lane = threadIdx.x & 31;
    if (gw >= NN) return;
    int s = g_rowptr[gw];
    int e = g_rowptr[gw + 1];
    float a0 = 0.f, a1 = 0.f, a2 = 0.f, a3 = 0.f, a4 = 0.f, a5 = 0.f;
    int i = s;
    for (; i + 4 <= e; i += 4) {
        int c0 = __ldg(&g_colidx[i]),     c1 = __ldg(&g_colidx[i + 1]);
        int c2 = __ldg(&g_colidx[i + 2]), c3 = __ldg(&g_colidx[i + 3]);
        float w0 = __ldg(&g_ew[i]),     w1 = __ldg(&g_ew[i + 1]);
        float w2 = __ldg(&g_ew[i + 2]), w3 = __ldg(&g_ew[i + 3]);
        uint2 p0 = __ldg(reinterpret_cast<const uint2*>(hin + (size_t)c0 * F) + lane);
        uint2 p1 = __ldg(reinterpret_cast<const uint2*>(hin + (size_t)c1 * F) + lane);
        uint2 p2 = __ldg(reinterpret_cast<const uint2*>(hin + (size_t)c2 * F) + lane);
        uint2 p3 = __ldg(reinterpret_cast<const uint2*>(hin + (size_t)c3 * F) + lane);
        unsigned q0 = 0, q1 = 0, q2 = 0, q3 = 0;
        if (F == 192) {
            q0 = __ldg(reinterpret_cast<const unsigned*>(hin + (size_t)c0 * F + 128) + lane);
            q1 = __ldg(reinterpret_cast<const unsigned*>(hin + (size_t)c1 * F + 128) + lane);
            q2 = __ldg(reinterpret_cast<const unsigned*>(hin + (size_t)c2 * F + 128) + lane);
            q3 = __ldg(reinterpret_cast<const unsigned*>(hin + (size_t)c3 * F + 128) + lane);
        }
#define CONS(P, Q, W) { \
        float2 f0 = bfu2f2(P.x), f1 = bfu2f2(P.y); \
        a0 = fmaf(W, f0.x, a0); a1 = fmaf(W, f0.y, a1); \
        a2 = fmaf(W, f1.x, a2); a3 = fmaf(W, f1.y, a3); \
        if (F == 192) { float2 f2 = bfu2f2(Q); a4 = fmaf(W, f2.x, a4); a5 = fmaf(W, f2.y, a5); } }
        CONS(p0, q0, w0); CONS(p1, q1, w1); CONS(p2, q2, w2); CONS(p3, q3, w3);
    }
    for (; i < e; i++) {
        int c = __ldg(&g_colidx[i]);
        float w = __ldg(&g_ew[i]);
        uint2 p = __ldg(reinterpret_cast<const uint2*>(hin + (size_t)c * F) + lane);
        unsigned q = 0;
        if (F == 192) q = __ldg(reinterpret_cast<const unsigned*>(hin + (size_t)c * F + 128) + lane);
        CONS(p, q, w);
    }
#undef CONS
    __nv_bfloat16* b = bout + (size_t)gw * F;
    __nv_bfloat162 b0 = __float22bfloat162_rn(make_float2(a0, a1));
    __nv_bfloat162 b1 = __float22bfloat162_rn(make_float2(a2, a3));
    uint2 pp;
    pp.x = *reinterpret_cast<unsigned*>(&b0);
    pp.y = *reinterpret_cast<unsigned*>(&b1);
    reinterpret_cast<uint2*>(b)[lane] = pp;
    if (F == 192) {
        __nv_bfloat162 b2 = __float22bfloat162_rn(make_float2(a4, a5));
        reinterpret_cast<unsigned*>(b + 128)[lane] = *reinterpret_cast<unsigned*>(&b2);
    }
}

// ---------------- weight fold + transpose: [Fo][K3], bf16 hi/lo split ----------------
__global__ void prep_wT(const float* __restrict__ W, int Fin, int Fo) {
    int i = blockIdx.x * blockDim.x + threadIdx.x;
    int K3 = 3 * Fin;
    if (i >= Fo * K3) return;
    int o = i / K3, j = i - o * K3;
    int term = j / Fin, ii = j - term * Fin;
    float v;
    if (term == 0)      v = W[(size_t)ii * Fo + o] - W[(size_t)(2 * Fin + ii) * Fo + o];
    else if (term == 1) v = W[(size_t)(Fin + ii) * Fo + o];
    else                v = 2.f * W[(size_t)(2 * Fin + ii) * Fo + o];
    __nv_bfloat16 hi = __float2bfloat16(v);
    g_wbh[i] = hi;
    g_wbl[i] = __float2bfloat16(v - __bfloat162float(hi));
}

// ---------------- bf16 m16n8k16 tensor-core GEMM: out = [h|t1|t2] @ wT^T + bias ----------------
#define ASTR 20   // words per 32-k row (16 + 4 pad): conflict-free fragment reads, 16B-aligned

#define MMA_BF16(c, A_, B_) \
    asm volatile("mma.sync.aligned.m16n8k16.row.col.f32.bf16.bf16.f32 " \
                 "{%0,%1,%2,%3},{%4,%5,%6,%7},{%8,%9},{%0,%1,%2,%3};" \
                 : "+f"((c)[0]), "+f"((c)[1]), "+f"((c)[2]), "+f"((c)[3]) \
                 : "r"((A_)[0]), "r"((A_)[1]), "r"((A_)[2]), "r"((A_)[3]), \
                   "r"((B_)[0]), "r"((B_)[1]))

__global__ __launch_bounds__(128) void gemm_cheb(
    const __nv_bfloat16* __restrict__ h, const __nv_bfloat16* __restrict__ t1p,
    const __nv_bfloat16* __restrict__ t2p, const float* __restrict__ bias,
    __nv_bfloat16* __restrict__ outb, int Fin, int Fo)
{
    __shared__ __align__(16) unsigned As[128 * ASTR];   // 128 rows x 32 k (bf16x2 words)
    __shared__ __align__(16) unsigned BsH[64 * ASTR];   // 64 cols x 32 k
    __shared__ __align__(16) unsigned BsL[64 * ASTR];

    int tid = threadIdx.x;
    int lane = tid & 31;
    int warp = tid >> 5;
    int wm = warp >> 1;          // 0..1 (64-row half)
    int wn = warp & 1;           // 0..1 (32-col half)
    int tile_m = blockIdx.x * 128;
    int tile_n = blockIdx.y * 64;
    int K3 = 3 * Fin;
    const __nv_bfloat16* bufs[3] = { h, t1p, t2p };

    float acc[4][4][4];
#pragma unroll
    for (int a = 0; a < 4; a++)
#pragma unroll
        for (int b = 0; b < 4; b++)
#pragma unroll
            for (int c = 0; c < 4; c++) acc[a][b][c] = 0.f;

    for (int k0 = 0; k0 < K3; k0 += 32) {
        const __nv_bfloat16* A = bufs[k0 / Fin];
        int kl = k0 % Fin;
        // stage A: 128 rows x 32 k = 512 uint4 copies (bf16 direct, no conversion)
#pragma unroll
        for (int j = 0; j < 4; j++) {
            int idx = j * 128 + tid;
            int m = idx >> 2, kq = idx & 3;
            int gm = tile_m + m;
            uint4 v = make_uint4(0u, 0u, 0u, 0u);
            if (gm < NN)
                v = *reinterpret_cast<const uint4*>(A + (size_t)gm * Fin + kl + kq * 8);
            *reinterpret_cast<uint4*>(&As[m * ASTR + kq * 4]) = v;
        }
        // stage B hi/lo: 64 cols x 32 k = 256 uint4 each
#pragma unroll
        for (int j = 0; j < 2; j++) {
            int idx = j * 128 + tid;
            int n = idx >> 2, kq = idx & 3;
            size_t gsrc = (size_t)(tile_n + n) * K3 + k0 + kq * 8;
            *reinterpret_cast<uint4*>(&BsH[n * ASTR + kq * 4]) =
                *reinterpret_cast<const uint4*>(g_wbh + gsrc);
            *reinterpret_cast<uint4*>(&BsL[n * ASTR + kq * 4]) =
                *reinterpret_cast<const uint4*>(g_wbl + gsrc);
        }
        __syncthreads();

#pragma unroll
        for (int ks = 0; ks < 2; ks++) {       // two k16 steps per 32-k block
            unsigned a[4][4], bh[4][2], bl[4][2];
#pragma unroll
            for (int mt = 0; mt < 4; mt++) {
                int base = (wm * 64 + mt * 16 + (lane >> 2)) * ASTR + ks * 8 + (lane & 3);
                a[mt][0] = As[base];
                a[mt][1] = As[base + 8 * ASTR];
                a[mt][2] = As[base + 4];
                a[mt][3] = As[base + 8 * ASTR + 4];
            }
#pragma unroll
            for (int nt = 0; nt < 4; nt++) {
                int cb = (wn * 32 + nt * 8 + (lane >> 2)) * ASTR + ks * 8 + (lane & 3);
                bh[nt][0] = BsH[cb];
                bh[nt][1] = BsH[cb + 4];
                bl[nt][0] = BsL[cb];
                bl[nt][1] = BsL[cb + 4];
            }
#pragma unroll
            for (int mt = 0; mt < 4; mt++)
#pragma unroll
                for (int nt = 0; nt < 4; nt++) {
                    MMA_BF16(acc[mt][nt], a[mt], bh[nt]);
                    MMA_BF16(acc[mt][nt], a[mt], bl[nt]);
                }
        }
        __syncthreads();
    }

    // epilogue: bias + bf16 output
#pragma unroll
    for (int mt = 0; mt < 4; mt++) {
        int r0 = tile_m + wm * 64 + mt * 16 + (lane >> 2);
#pragma unroll
        for (int nt = 0; nt < 4; nt++) {
            int c0 = tile_n + wn * 32 + nt * 8 + 2 * (lane & 3);
            float2 bb = *reinterpret_cast<const float2*>(bias + c0);
            if (r0 < NN) {
                __nv_bfloat162 o = __float22bfloat162_rn(
                    make_float2(acc[mt][nt][0] + bb.x, acc[mt][nt][1] + bb.y));
                *reinterpret_cast<__nv_bfloat162*>(outb + (size_t)r0 * Fo + c0) = o;
            }
            if (r0 + 8 < NN) {
                __nv_bfloat162 o = __float22bfloat162_rn(
                    make_float2(acc[mt][nt][2] + bb.x, acc[mt][nt][3] + bb.y));
                *reinterpret_cast<__nv_bfloat162*>(outb + (size_t)(r0 + 8) * Fo + c0) = o;
            }
        }
    }
}

// ---------------- global mean pool (bf16 input) ----------------
__global__ void pool_kernel(const __nv_bfloat16* __restrict__ h, const int* __restrict__ batch) {
    int t = threadIdx.x;
    int base = blockIdx.x * 128;
    int cur = -1;
    float acc = 0.f;
    int cnt = 0;
    for (int n = 0; n < 128; n++) {
        int g = base + n;
        if (g >= NN) break;
        int bg = batch[g];
        if (bg != cur) {
            if (cur >= 0) {
                atomicAdd(&g_pool[cur * FO + t], acc);
                if (t == 0) atomicAdd(&g_cnt[cur], cnt);
            }
            cur = bg; acc = 0.f; cnt = 0;
        }
        acc += __bfloat162float(h[(size_t)g * FO + t]);
        cnt++;
    }
    if (cur >= 0) {
        atomicAdd(&g_pool[cur * FO + t], acc);
        if (t == 0) atomicAdd(&g_cnt[cur], cnt);
    }
}

// ---------------- FC + log_softmax ----------------
__global__ void final_kernel(const float* __restrict__ fcw, const float* __restrict__ fcb,
                             float* __restrict__ out) {
    __shared__ float lg[NG][NC];
    __shared__ float smax[NG], slse[NG];
    int t = threadIdx.x;
    if (t < NG * NC) {
        int g = t / NC, c = t % NC;
        float inv = 1.f / fmaxf((float)g_cnt[g], 1.f);
        float s = fcb[c];
        for (int f = 0; f < FO; f++)
            s = fmaf(g_pool[g * FO + f] * inv, fcw[f * NC + c], s);
        lg[g][c] = s;
    }
    __syncthreads();
    if (t < NG) {
        float m = -1e30f;
        for (int c = 0; c < NC; c++) m = fmaxf(m, lg[t][c]);
        float se = 0.f;
        for (int c = 0; c < NC; c++) se += expf(lg[t][c] - m);
        smax[t] = m;
        slse[t] = logf(se);
    }
    __syncthreads();
    if (t < NG * NC) {
        int g = t / NC, c = t % NC;
        out[t] = lg[g][c] - smax[g] - slse[g];
    }
}

// ---------------- launch ----------------
extern "C" void kernel_launch(void* const* d_in, const int* in_sizes, int n_in,
                              void* d_out, int out_size) {
    const float* x   = (const float*)d_in[0];
    const int*   ei  = (const int*)d_in[1];
    const int*   bat = (const int*)d_in[2];
    const float* W1  = (const float*)d_in[3];
    const float* b1  = (const float*)d_in[4];
    const float* W2  = (const float*)d_in[5];
    const float* b2  = (const float*)d_in[6];
    const float* W3  = (const float*)d_in[7];
    const float* b3  = (const float*)d_in[8];
    const float* fcw = (const float*)d_in[9];
    const float* fcb = (const float*)d_in[10];
    float* out = (float*)d_out;

    __nv_bfloat16 *xb, *t1b, *t2b, *h1b, *h2b, *h3b;
    cudaGetSymbolAddress((void**)&xb,  g_xb);
    cudaGetSymbolAddress((void**)&t1b, g_t1b);
    cudaGetSymbolAddress((void**)&t2b, g_t2b);
    cudaGetSymbolAddress((void**)&h1b, g_h1b);
    cudaGetSymbolAddress((void**)&h2b, g_h2b);
    cudaGetSymbolAddress((void**)&h3b, g_h3b);

    const int NB = (NN + 255) / 256;

    zero_kernel<<<(NN + 255) / 256, 256>>>();
    hist_kernel<<<(NE + 255) / 256, 256>>>(ei);
    dis_kernel<<<(NN + 255) / 256, 256>>>();
    conv_x_kernel<<<(NN * FI / 4 + 255) / 256, 256>>>(x);
    scan1_kernel<<<NB, 256>>>();
    scan2_kernel<<<1, 256>>>(NB);
    scan3_kernel<<<NB, 256>>>();
    fill_kernel<<<(NE + 255) / 256, 256>>>(ei);

    const int spmmBlocks = (NN * 32 + 255) / 256;
    dim3 gemmGridH((NN + 127) / 128, FH / 64);
    dim3 gemmGridO((NN + 127) / 128, FO / 64);

    // layer 1: Fin=128 -> Fo=192
    spmm_kernel<FI><<<spmmBlocks, 256>>>(xb, t1b);
    spmm_kernel<FI><<<spmmBlocks, 256>>>(t1b, t2b);
    prep_wT<<<(FH * 3 * FI + 255) / 256, 256>>>(W1, FI, FH);
    gemm_cheb<<<gemmGridH, 128>>>(xb, t1b, t2b, b1, h1b, FI, FH);

    // layer 2: Fin=192 -> Fo=192
    spmm_kernel<FH><<<spmmBlocks, 256>>>(h1b, t1b);
    spmm_kernel<FH><<<spmmBlocks, 256>>>(t1b, t2b);
    prep_wT<<<(FH * 3 * FH + 255) / 256, 256>>>(W2, FH, FH);
    gemm_cheb<<<gemmGridH, 128>>>(h1b, t1b, t2b, b2, h2b, FH, FH);

    // layer 3: Fin=192 -> Fo=128
    spmm_kernel<FH><<<spmmBlocks, 256>>>(h2b, t1b);
    spmm_kernel<FH><<<spmmBlocks, 256>>>(t1b, t2b);
    prep_wT<<<(FO * 3 * FH + 255) / 256, 256>>>(W3, FH, FO);
    gemm_cheb<<<gemmGridO, 128>>>(h2b, t1b, t2b, b3, h3b, FH, FO);

    pool_kernel<<<(NN + 127) / 128, 128>>>(h3b, bat);
    final_kernel<<<1, 640>>>(fcw, fcb, out);
}

// round 15
// speedup vs baseline: 2.5244x; 1.0437x over previous
#include <cuda_runtime.h>
#include <cuda_bf16.h>
#include <stdint.h>
#include <math.h>

#define NN 50000
#define NE 800000
#define NG 64
#define FI 128
#define FH 192
#define FO 128
#define NC 10

// ---------------- device scratch ----------------
__device__ int   g_deg[NN];
__device__ int   g_fill[NN];
__device__ float g_dis[NN];
__device__ int   g_rowptr[NN + 1];
__device__ int   g_bsum[256];
__device__ int   g_boff[256];
__device__ int   g_colidx[NE];
__device__ float g_ew[NE];

__device__ __align__(16) __nv_bfloat16 g_xb[(size_t)NN * FI];
__device__ __align__(16) __nv_bfloat16 g_t1b[(size_t)NN * FH];
__device__ __align__(16) __nv_bfloat16 g_t2b[(size_t)NN * FH];
__device__ __align__(16) __nv_bfloat16 g_h1b[(size_t)NN * FH];
__device__ __align__(16) __nv_bfloat16 g_h2b[(size_t)NN * FH];
__device__ __align__(16) __nv_bfloat16 g_h3b[(size_t)NN * FO];
__device__ __align__(16) __nv_bfloat16 g_wbh[FH * 3 * FH];   // [Fo][K3] hi (folded, transposed)
__device__ __align__(16) __nv_bfloat16 g_wbl[FH * 3 * FH];   // [Fo][K3] lo
__device__ float g_pool[NG * FO];
__device__ int   g_cnt[NG];

__device__ __forceinline__ float2 bfu2f2(unsigned u) {
    __nv_bfloat162 b = *reinterpret_cast<__nv_bfloat162*>(&u);
    return __bfloat1622float2(b);
}

// ---------------- graph prep ----------------
__global__ void zero_kernel() {
    int i = blockIdx.x * blockDim.x + threadIdx.x;
    if (i < NN) { g_deg[i] = 0; g_fill[i] = 0; }
    if (i < NG * FO) g_pool[i] = 0.f;
    if (i < NG) g_cnt[i] = 0;
}
__global__ void hist_kernel(const int* __restrict__ ei) {
    int e = blockIdx.x * blockDim.x + threadIdx.x;
    if (e < NE) atomicAdd(&g_deg[ei[e]], 1);
}
__global__ void dis_kernel() {
    int i = blockIdx.x * blockDim.x + threadIdx.x;
    if (i < NN) {
        int d = g_deg[i];
        g_dis[i] = (d > 0) ? rsqrtf((float)d) : 0.f;
    }
}
__global__ void conv_x_kernel(const float* __restrict__ x) {
    int i = blockIdx.x * blockDim.x + threadIdx.x;
    if (i < NN * FI / 4) {
        float4 v = __ldg(reinterpret_cast<const float4*>(x) + i);
        __nv_bfloat162 a = __float22bfloat162_rn(make_float2(v.x, v.y));
        __nv_bfloat162 b = __float22bfloat162_rn(make_float2(v.z, v.w));
        reinterpret_cast<__nv_bfloat162*>(g_xb)[2 * i] = a;
        reinterpret_cast<__nv_bfloat162*>(g_xb)[2 * i + 1] = b;
    }
}
__global__ void scan1_kernel() {
    __shared__ int ws[8];
    int t = threadIdx.x, b = blockIdx.x;
    int lane = t & 31, w = t >> 5;
    int i = b * 256 + t;
    int v = (i < NN) ? g_deg[i] : 0;
    int incl = v;
#pragma unroll
    for (int d = 1; d < 32; d <<= 1) {
        int n = __shfl_up_sync(0xffffffff, incl, d);
        if (lane >= d) incl += n;
    }
    if (lane == 31) ws[w] = incl;
    __syncthreads();
    if (w == 0 && lane < 8) {
        int s = ws[lane];
#pragma unroll
        for (int d = 1; d < 8; d <<= 1) {
            int n = __shfl_up_sync(0xff, s, d);
            if (lane >= d) s += n;
        }
        ws[lane] = s;
    }
    __syncthreads();
    int off = (w > 0) ? ws[w - 1] : 0;
    incl += off;
    if (i < NN) g_rowptr[i + 1] = incl;
    if (t == 255) g_bsum[b] = incl;
}
__global__ void scan2_kernel(int nblk) {
    __shared__ int ws[8];
    int t = threadIdx.x;
    int lane = t & 31, w = t >> 5;
    int v = (t < nblk) ? g_bsum[t] : 0;
    int incl = v;
#pragma unroll
    for (int d = 1; d < 32; d <<= 1) {
        int n = __shfl_up_sync(0xffffffff, incl, d);
        if (lane >= d) incl += n;
    }
    if (lane == 31) ws[w] = incl;
    __syncthreads();
    if (w == 0 && lane < 8) {
        int s = ws[lane];
#pragma unroll
        for (int d = 1; d < 8; d <<= 1) {
            int n = __shfl_up_sync(0xff, s, d);
            if (lane >= d) s += n;
        }
        ws[lane] = s;
    }
    __syncthreads();
    int off = (w > 0) ? ws[w - 1] : 0;
    g_boff[t] = incl + off - v;
    if (t == 0) g_rowptr[0] = 0;
}
__global__ void scan3_kernel() {
    int i = blockIdx.x * blockDim.x + threadIdx.x;
    if (i < NN) g_rowptr[i + 1] += g_boff[i >> 8];
}
__global__ void fill_kernel(const int* __restrict__ ei) {
    int e = blockIdx.x * blockDim.x + threadIdx.x;
    if (e >= NE) return;
    int r = ei[e];
    int c = ei[NE + e];
    int p = g_rowptr[r] + atomicAdd(&g_fill[r], 1);
    g_colidx[p] = c;
    g_ew[p] = -g_dis[r] * g_dis[c];
}

// ---------------- SpMM: bf16 gather, fp32 accumulate, bf16 out, MLP=8 ----------------
template <int F>
__global__ void spmm_kernel(const __nv_bfloat16* __restrict__ hin,
                            __nv_bfloat16* __restrict__ bout) {
    int gw = (int)((blockIdx.x * (size_t)blockDim.x + threadIdx.x) >> 5);
    int lane = threadIdx.x & 31;
    if (gw >= NN) return;
    int s = g_rowptr[gw];
    int e = g_rowptr[gw + 1];
    float a0 = 0.f, a1 = 0.f, a2 = 0.f, a3 = 0.f, a4 = 0.f, a5 = 0.f;
    int i = s;
#define CONS(P, Q, W) { \
        float2 f0 = bfu2f2(P.x), f1 = bfu2f2(P.y); \
        a0 = fmaf(W, f0.x, a0); a1 = fmaf(W, f0.y, a1); \
        a2 = fmaf(W, f1.x, a2); a3 = fmaf(W, f1.y, a3); \
        if (F == 192) { float2 f2 = bfu2f2(Q); a4 = fmaf(W, f2.x, a4); a5 = fmaf(W, f2.y, a5); } }
    for (; i + 8 <= e; i += 8) {
        int cc[8]; float ww[8]; uint2 pp[8]; unsigned qq[8];
#pragma unroll
        for (int u = 0; u < 8; u++) {
            cc[u] = __ldg(&g_colidx[i + u]);
            ww[u] = __ldg(&g_ew[i + u]);
        }
#pragma unroll
        for (int u = 0; u < 8; u++) {
            pp[u] = __ldg(reinterpret_cast<const uint2*>(hin + (size_t)cc[u] * F) + lane);
            if (F == 192)
                qq[u] = __ldg(reinterpret_cast<const unsigned*>(hin + (size_t)cc[u] * F + 128) + lane);
            else qq[u] = 0;
        }
#pragma unroll
        for (int u = 0; u < 8; u++) CONS(pp[u], qq[u], ww[u]);
    }
    for (; i < e; i++) {
        int c = __ldg(&g_colidx[i]);
        float w = __ldg(&g_ew[i]);
        uint2 p = __ldg(reinterpret_cast<const uint2*>(hin + (size_t)c * F) + lane);
        unsigned q = 0;
        if (F == 192) q = __ldg(reinterpret_cast<const unsigned*>(hin + (size_t)c * F + 128) + lane);
        CONS(p, q, w);
    }
#undef CONS
    __nv_bfloat16* b = bout + (size_t)gw * F;
    __nv_bfloat162 b0 = __float22bfloat162_rn(make_float2(a0, a1));
    __nv_bfloat162 b1 = __float22bfloat162_rn(make_float2(a2, a3));
    uint2 pw;
    pw.x = *reinterpret_cast<unsigned*>(&b0);
    pw.y = *reinterpret_cast<unsigned*>(&b1);
    reinterpret_cast<uint2*>(b)[lane] = pw;
    if (F == 192) {
        __nv_bfloat162 b2 = __float22bfloat162_rn(make_float2(a4, a5));
        reinterpret_cast<unsigned*>(b + 128)[lane] = *reinterpret_cast<unsigned*>(&b2);
    }
}

// ---------------- weight fold + transpose: [Fo][K3], bf16 hi/lo split ----------------
__global__ void prep_wT(const float* __restrict__ W, int Fin, int Fo) {
    int i = blockIdx.x * blockDim.x + threadIdx.x;
    int K3 = 3 * Fin;
    if (i >= Fo * K3) return;
    int o = i / K3, j = i - o * K3;
    int term = j / Fin, ii = j - term * Fin;
    float v;
    if (term == 0)      v = W[(size_t)ii * Fo + o] - W[(size_t)(2 * Fin + ii) * Fo + o];
    else if (term == 1) v = W[(size_t)(Fin + ii) * Fo + o];
    else                v = 2.f * W[(size_t)(2 * Fin + ii) * Fo + o];
    __nv_bfloat16 hi = __float2bfloat16(v);
    g_wbh[i] = hi;
    g_wbl[i] = __float2bfloat16(v - __bfloat162float(hi));
}

// ---------------- bf16 m16n8k16 GEMM with ldmatrix fragment loads ----------------
#define ASTR 20   // words per 32-k row (16 + 4 pad): stride-20 tiles all 32 banks per ldmatrix phase

#define MMA_BF16(c, A_, B_) \
    asm volatile("mma.sync.aligned.m16n8k16.row.col.f32.bf16.bf16.f32 " \
                 "{%0,%1,%2,%3},{%4,%5,%6,%7},{%8,%9},{%0,%1,%2,%3};" \
                 : "+f"((c)[0]), "+f"((c)[1]), "+f"((c)[2]), "+f"((c)[3]) \
                 : "r"((A_)[0]), "r"((A_)[1]), "r"((A_)[2]), "r"((A_)[3]), \
                   "r"((B_)[0]), "r"((B_)[1]))

#define LDSM4(r0, r1, r2, r3, addr) \
    asm volatile("ldmatrix.sync.aligned.m8n8.x4.shared.b16 {%0,%1,%2,%3}, [%4];" \
                 : "=r"(r0), "=r"(r1), "=r"(r2), "=r"(r3) : "r"(addr))

__global__ __launch_bounds__(128) void gemm_cheb(
    const __nv_bfloat16* __restrict__ h, const __nv_bfloat16* __restrict__ t1p,
    const __nv_bfloat16* __restrict__ t2p, const float* __restrict__ bias,
    __nv_bfloat16* __restrict__ outb, int Fin, int Fo)
{
    __shared__ __align__(16) unsigned As[128 * ASTR];   // 128 rows x 32 k (bf16x2 words)
    __shared__ __align__(16) unsigned BsH[64 * ASTR];   // 64 cols x 32 k
    __shared__ __align__(16) unsigned BsL[64 * ASTR];

    int tid = threadIdx.x;
    int lane = tid & 31;
    int warp = tid >> 5;
    int wm = warp >> 1;          // 0..1 (64-row half)
    int wn = warp & 1;           // 0..1 (32-col half)
    int tile_m = blockIdx.x * 128;
    int tile_n = blockIdx.y * 64;
    int K3 = 3 * Fin;
    const __nv_bfloat16* bufs[3] = { h, t1p, t2p };

    uint32_t sA  = (uint32_t)__cvta_generic_to_shared(As);
    uint32_t sBH = (uint32_t)__cvta_generic_to_shared(BsH);
    uint32_t sBL = (uint32_t)__cvta_generic_to_shared(BsL);

    // ldmatrix lane decomposition (x4: lanes 0-7 mat0, 8-15 mat1, 16-23 mat2, 24-31 mat3)
    int g  = lane >> 3;
    int lr = lane & 7;
    int a_row_lane = (g & 1) * 8 + lr;    // mat0/2: rows 0-7, mat1/3: rows 8-15
    int a_seg_lane = g >> 1;              // mat0/1: k0-7, mat2/3: k8-15
    int b_col_lane = (g >> 1) * 8 + lr;   // mat0/1: cols 0-7, mat2/3: cols 8-15
    int b_seg_lane = g & 1;               // mat0/2: k0-7, mat1/3: k8-15

    float acc[4][4][4];
#pragma unroll
    for (int a = 0; a < 4; a++)
#pragma unroll
        for (int b = 0; b < 4; b++)
#pragma unroll
            for (int c = 0; c < 4; c++) acc[a][b][c] = 0.f;

    for (int k0 = 0; k0 < K3; k0 += 32) {
        const __nv_bfloat16* A = bufs[k0 / Fin];
        int kl = k0 % Fin;
        // stage A: 128 rows x 32 k = 512 uint4 copies
#pragma unroll
        for (int j = 0; j < 4; j++) {
            int idx = j * 128 + tid;
            int m = idx >> 2, kq = idx & 3;
            int gm = tile_m + m;
            uint4 v = make_uint4(0u, 0u, 0u, 0u);
            if (gm < NN)
                v = *reinterpret_cast<const uint4*>(A + (size_t)gm * Fin + kl + kq * 8);
            *reinterpret_cast<uint4*>(&As[m * ASTR + kq * 4]) = v;
        }
        // stage B hi/lo: 64 cols x 32 k
#pragma unroll
        for (int j = 0; j < 2; j++) {
            int idx = j * 128 + tid;
            int n = idx >> 2, kq = idx & 3;
            size_t gsrc = (size_t)(tile_n + n) * K3 + k0 + kq * 8;
            *reinterpret_cast<uint4*>(&BsH[n * ASTR + kq * 4]) =
                *reinterpret_cast<const uint4*>(g_wbh + gsrc);
            *reinterpret_cast<uint4*>(&BsL[n * ASTR + kq * 4]) =
                *reinterpret_cast<const uint4*>(g_wbl + gsrc);
        }
        __syncthreads();

#pragma unroll
        for (int ks = 0; ks < 2; ks++) {
            unsigned a[4][4], bh[4][2], bl[4][2];
#pragma unroll
            for (int mt = 0; mt < 4; mt++) {
                uint32_t ad = sA + (uint32_t)(((wm * 64 + mt * 16 + a_row_lane) * ASTR
                              + (ks * 2 + a_seg_lane) * 4) * 4);
                LDSM4(a[mt][0], a[mt][1], a[mt][2], a[mt][3], ad);
            }
#pragma unroll
            for (int p = 0; p < 2; p++) {
                uint32_t off = (uint32_t)(((wn * 32 + p * 16 + b_col_lane) * ASTR
                              + (ks * 2 + b_seg_lane) * 4) * 4);
                LDSM4(bh[2 * p][0], bh[2 * p][1], bh[2 * p + 1][0], bh[2 * p + 1][1], sBH + off);
                LDSM4(bl[2 * p][0], bl[2 * p][1], bl[2 * p + 1][0], bl[2 * p + 1][1], sBL + off);
            }
#pragma unroll
            for (int mt = 0; mt < 4; mt++)
#pragma unroll
                for (int nt = 0; nt < 4; nt++) {
                    MMA_BF16(acc[mt][nt], a[mt], bh[nt]);
                    MMA_BF16(acc[mt][nt], a[mt], bl[nt]);
                }
        }
        __syncthreads();
    }

    // epilogue: bias + bf16 output
#pragma unroll
    for (int mt = 0; mt < 4; mt++) {
        int r0 = tile_m + wm * 64 + mt * 16 + (lane >> 2);
#pragma unroll
        for (int nt = 0; nt < 4; nt++) {
            int c0 = tile_n + wn * 32 + nt * 8 + 2 * (lane & 3);
            float2 bb = *reinterpret_cast<const float2*>(bias + c0);
            if (r0 < NN) {
                __nv_bfloat162 o = __float22bfloat162_rn(
                    make_float2(acc[mt][nt][0] + bb.x, acc[mt][nt][1] + bb.y));
                *reinterpret_cast<__nv_bfloat162*>(outb + (size_t)r0 * Fo + c0) = o;
            }
            if (r0 + 8 < NN) {
                __nv_bfloat162 o = __float22bfloat162_rn(
                    make_float2(acc[mt][nt][2] + bb.x, acc[mt][nt][3] + bb.y));
                *reinterpret_cast<__nv_bfloat162*>(outb + (size_t)(r0 + 8) * Fo + c0) = o;
            }
        }
    }
}

// ---------------- global mean pool (bf16 input) ----------------
__global__ void pool_kernel(const __nv_bfloat16* __restrict__ h, const int* __restrict__ batch) {
    int t = threadIdx.x;
    int base = blockIdx.x * 128;
    int cur = -1;
    float acc = 0.f;
    int cnt = 0;
    for (int n = 0; n < 128; n++) {
        int g = base + n;
        if (g >= NN) break;
        int bg = batch[g];
        if (bg != cur) {
            if (cur >= 0) {
                atomicAdd(&g_pool[cur * FO + t], acc);
                if (t == 0) atomicAdd(&g_cnt[cur], cnt);
            }
            cur = bg; acc = 0.f; cnt = 0;
        }
        acc += __bfloat162float(h[(size_t)g * FO + t]);
        cnt++;
    }
    if (cur >= 0) {
        atomicAdd(&g_pool[cur * FO + t], acc);
        if (t == 0) atomicAdd(&g_cnt[cur], cnt);
    }
}

// ---------------- FC + log_softmax ----------------
__global__ void final_kernel(const float* __restrict__ fcw, const float* __restrict__ fcb,
                             float* __restrict__ out) {
    __shared__ float lg[NG][NC];
    __shared__ float smax[NG], slse[NG];
    int t = threadIdx.x;
    if (t < NG * NC) {
        int g = t / NC, c = t % NC;
        float inv = 1.f / fmaxf((float)g_cnt[g], 1.f);
        float s = fcb[c];
        for (int f = 0; f < FO; f++)
            s = fmaf(g_pool[g * FO + f] * inv, fcw[f * NC + c], s);
        lg[g][c] = s;
    }
    __syncthreads();
    if (t < NG) {
        float m = -1e30f;
        for (int c = 0; c < NC; c++) m = fmaxf(m, lg[t][c]);
        float se = 0.f;
        for (int c = 0; c < NC; c++) se += expf(lg[t][c] - m);
        smax[t] = m;
        slse[t] = logf(se);
    }
    __syncthreads();
    if (t < NG * NC) {
        int g = t / NC, c = t % NC;
        out[t] = lg[g][c] - smax[g] - slse[g];
    }
}

// ---------------- launch ----------------
extern "C" void kernel_launch(void* const* d_in, const int* in_sizes, int n_in,
                              void* d_out, int out_size) {
    const float* x   = (const float*)d_in[0];
    const int*   ei  = (const int*)d_in[1];
    const int*   bat = (const int*)d_in[2];
    const float* W1  = (const float*)d_in[3];
    const float* b1  = (const float*)d_in[4];
    const float* W2  = (const float*)d_in[5];
    const float* b2  = (const float*)d_in[6];
    const float* W3  = (const float*)d_in[7];
    const float* b3  = (const float*)d_in[8];
    const float* fcw = (const float*)d_in[9];
    const float* fcb = (const float*)d_in[10];
    float* out = (float*)d_out;

    __nv_bfloat16 *xb, *t1b, *t2b, *h1b, *h2b, *h3b;
    cudaGetSymbolAddress((void**)&xb,  g_xb);
    cudaGetSymbolAddress((void**)&t1b, g_t1b);
    cudaGetSymbolAddress((void**)&t2b, g_t2b);
    cudaGetSymbolAddress((void**)&h1b, g_h1b);
    cudaGetSymbolAddress((void**)&h2b, g_h2b);
    cudaGetSymbolAddress((void**)&h3b, g_h3b);

    const int NB = (NN + 255) / 256;

    zero_kernel<<<(NN + 255) / 256, 256>>>();
    hist_kernel<<<(NE + 255) / 256, 256>>>(ei);
    dis_kernel<<<(NN + 255) / 256, 256>>>();
    conv_x_kernel<<<(NN * FI / 4 + 255) / 256, 256>>>(x);
    scan1_kernel<<<NB, 256>>>();
    scan2_kernel<<<1, 256>>>(NB);
    scan3_kernel<<<NB, 256>>>();
    fill_kernel<<<(NE + 255) / 256, 256>>>(ei);

    const int spmmBlocks = (NN * 32 + 255) / 256;
    dim3 gemmGridH((NN + 127) / 128, FH / 64);
    dim3 gemmGridO((NN + 127) / 128, FO / 64);

    // layer 1: Fin=128 -> Fo=192
    spmm_kernel<FI><<<spmmBlocks, 256>>>(xb, t1b);
    spmm_kernel<FI><<<spmmBlocks, 256>>>(t1b, t2b);
    prep_wT<<<(FH * 3 * FI + 255) / 256, 256>>>(W1, FI, FH);
    gemm_cheb<<<gemmGridH, 128>>>(xb, t1b, t2b, b1, h1b, FI, FH);

    // layer 2: Fin=192 -> Fo=192
    spmm_kernel<FH><<<spmmBlocks, 256>>>(h1b, t1b);
    spmm_kernel<FH><<<spmmBlocks, 256>>>(t1b, t2b);
    prep_wT<<<(FH * 3 * FH + 255) / 256, 256>>>(W2, FH, FH);
    gemm_cheb<<<gemmGridH, 128>>>(h1b, t1b, t2b, b2, h2b, FH, FH);

    // layer 3: Fin=192 -> Fo=128
    spmm_kernel<FH><<<spmmBlocks, 256>>>(h2b, t1b);
    spmm_kernel<FH><<<spmmBlocks, 256>>>(t1b, t2b);
    prep_wT<<<(FO * 3 * FH + 255) / 256, 256>>>(W3, FH, FO);
    gemm_cheb<<<gemmGridO, 128>>>(h2b, t1b, t2b, b3, h3b, FH, FO);

    pool_kernel<<<(NN + 127) / 128, 128>>>(h3b, bat);
    final_kernel<<<1, 640>>>(fcw, fcb, out);
}